// round 14
// baseline (speedup 1.0000x reference)
#include <cuda_runtime.h>
#include <cstdint>

// ---------------------------------------------------------------------------
// Problem constants
//   B=8, CIN=16, HID=64, T=4, W=32, H=32, TAU=5
//   SP  = T*W*H          = 4096
//   CSP = HID*SP         = 262144
//   VOL = B*CSP          = 2097152
// Output layout: c_history_new[5*VOL], m_new[VOL], h_new[VOL]
// ---------------------------------------------------------------------------
#define SP   4096
#define CSP  262144
#define VOL  2097152
#define EPSF 1e-5f

__device__ float g_u[7u * (unsigned)VOL];   // u0..u5 gates, u6 = o-branch
__device__ float g_wxT[7 * 16 * 27 * 64];   // Wx -> [k][ci][tap][co]
__device__ float g_whT[9 * 64 * 27 * 64];   // Wh -> [k][ci][tap][co]
__device__ float g_w111T[128 * 64];         // w111 -> [ci][co]
__device__ float g_spart[640];              // attention score partials
__device__ float g_attn[40];                // [l][b]
__device__ float g_part[2048 * 2];          // LN4 per-block partials
__device__ float g_stats[16];               // LN4 per-b (sum,sumsq)

// ---------------------------------------------------------------------------
// helpers
// ---------------------------------------------------------------------------
__device__ __forceinline__ unsigned long long bcast2(float v) {
    unsigned long long r;
    asm("mov.b64 %0, {%1, %1};" : "=l"(r) : "f"(v));
    return r;
}
__device__ __forceinline__ void ffma2(unsigned long long& a, unsigned long long v,
                                      unsigned long long w) {
    asm("fma.rn.f32x2 %0, %1, %2, %0;" : "+l"(a) : "l"(v), "l"(w));
}
__device__ __forceinline__ void unpack2(unsigned long long a, float& lo, float& hi) {
    asm("mov.b64 {%0, %1}, %2;" : "=f"(lo), "=f"(hi) : "l"(a));
}

__device__ __forceinline__ void block_reduce2(float& a, float& b, float* sh) {
    const int lane = threadIdx.x & 31, wid = threadIdx.x >> 5;
    const int nw = blockDim.x >> 5;
#pragma unroll
    for (int o = 16; o; o >>= 1) {
        a += __shfl_down_sync(0xffffffffu, a, o);
        b += __shfl_down_sync(0xffffffffu, b, o);
    }
    if (lane == 0) { sh[wid] = a; sh[16 + wid] = b; }
    __syncthreads();
    if (wid == 0) {
        a = lane < nw ? sh[lane] : 0.f;
        b = lane < nw ? sh[16 + lane] : 0.f;
#pragma unroll
        for (int o = 8; o; o >>= 1) {
            a += __shfl_down_sync(0xffffffffu, a, o);
            b += __shfl_down_sync(0xffffffffu, b, o);
        }
        if (lane == 0) { sh[0] = a; sh[16] = b; }
    }
    __syncthreads();
    a = sh[0]; b = sh[16];
}

// ---------------------------------------------------------------------------
// Register-blocked 3x3x3 'same' conv accumulation. 512 threads.
// Thread: 2 adjacent w rows x 16 co (8 f32x2 pairs). Block: (b, t0, 8 w rows),
// all 64 co. Per tap: 4x LDS.128 weights reused across both w outputs; per
// (dt,dh): 4 input scalars reused across all dw. LDS wf/FFMA2 ~= 0.33 < 0.5.
// ---------------------------------------------------------------------------
__device__ __forceinline__ void conv_accum512(
    const float* __restrict__ in,   // [CI][4][32][32]
    const float* __restrict__ wT,   // [CI][27][64]
    int CI, int t0, int wbase,
    float* s_in,                    // [3*10*34] = 1020
    float* s_w,                     // [27*64]   = 1728
    unsigned long long acc[2][8])
{
    const int tid = threadIdx.x;
    const int slot = tid & 127;
    const int hh = slot & 31;           // lanes contiguous in h
    const int w0 = (slot >> 5) * 2;     // 0,2,4,6
    const int coq = tid >> 7;           // co quarter 0..3

    for (int ci = 0; ci < CI; ++ci) {
        __syncthreads();   // previous compute done before smem overwrite
        const float* ip = in + ci * SP;
#pragma unroll
        for (int u = 0; u < 2; ++u) {
            int idx = tid + u * 512;
            if (idx < 1020) {
                int dt = idx / 340;
                int rem = idx - dt * 340;
                int row = rem / 34;
                int col = rem - row * 34;
                int tt = t0 + dt - 1, ww = wbase + row - 1, ch = col - 1;
                float v = 0.f;
                if (((unsigned)tt < 4u) & ((unsigned)ww < 32u) & ((unsigned)ch < 32u))
                    v = ip[tt * 1024 + ww * 32 + ch];
                s_in[idx] = v;
            }
        }
        if (tid < 432)
            reinterpret_cast<float4*>(s_w)[tid] =
                reinterpret_cast<const float4*>(wT + ci * 1728)[tid];
        __syncthreads();

#pragma unroll
        for (int dt = 0; dt < 3; ++dt) {
#pragma unroll
            for (int dh = 0; dh < 3; ++dh) {
                float v[4];
#pragma unroll
                for (int r = 0; r < 4; ++r)
                    v[r] = s_in[(dt * 10 + w0 + r) * 34 + hh + dh];
#pragma unroll
                for (int dw = 0; dw < 3; ++dw) {
                    const ulonglong2* wq = reinterpret_cast<const ulonglong2*>(
                        s_w + (dt * 9 + dw * 3 + dh) * 64 + coq * 16);
                    ulonglong2 w01 = wq[0], w23 = wq[1], w45 = wq[2], w67 = wq[3];
                    unsigned long long v0 = bcast2(v[dw]);
                    unsigned long long v1 = bcast2(v[dw + 1]);
                    ffma2(acc[0][0], v0, w01.x); ffma2(acc[0][1], v0, w01.y);
                    ffma2(acc[0][2], v0, w23.x); ffma2(acc[0][3], v0, w23.y);
                    ffma2(acc[0][4], v0, w45.x); ffma2(acc[0][5], v0, w45.y);
                    ffma2(acc[0][6], v0, w67.x); ffma2(acc[0][7], v0, w67.y);
                    ffma2(acc[1][0], v1, w01.x); ffma2(acc[1][1], v1, w01.y);
                    ffma2(acc[1][2], v1, w23.x); ffma2(acc[1][3], v1, w23.y);
                    ffma2(acc[1][4], v1, w45.x); ffma2(acc[1][5], v1, w45.y);
                    ffma2(acc[1][6], v1, w67.x); ffma2(acc[1][7], v1, w67.y);
                }
            }
        }
    }
}

// ---------------------------------------------------------------------------
// prep: weight transposes
// ---------------------------------------------------------------------------
__global__ void prep_kernel(const float* __restrict__ Wx,
                            const float* __restrict__ Wh,
                            const float* __restrict__ w111) {
    int idx = blockIdx.x * 256 + threadIdx.x;
    if (idx < 193536) {                         // Wx: [7][64][16][27] -> [7][16][27][64]
        int co = idx & 63; int q = idx >> 6;
        int tap = q % 27;  int q2 = q / 27;
        int ci = q2 & 15;  int k = q2 >> 4;
        g_wxT[idx] = Wx[((k * 64 + co) * 16 + ci) * 27 + tap];
    } else if (idx < 1188864) {                 // Wh: [9][64][64][27] -> [9][64][27][64]
        int j = idx - 193536;
        int co = j & 63; int q = j >> 6;
        int tap = q % 27; int q2 = q / 27;
        int ci = q2 & 63; int k = q2 >> 6;
        g_whT[j] = Wh[((k * 64 + co) * 64 + ci) * 27 + tap];
    } else if (idx < 1197056) {                 // w111: [64][128] -> [128][64]
        int j = idx - 1188864;
        int co = j & 63; int ci = j >> 6;
        g_w111T[j] = w111[co * 128 + ci];
    }
}

// ---------------------------------------------------------------------------
// stage1: u_k = conv(x,Wx[k]) + conv(state_k,Wh[k]) + biases, k=0..6
// grid (4 wtiles, 4 t, 56 = k*8+b), 512 threads
// ---------------------------------------------------------------------------
__global__ void __launch_bounds__(512, 1)
stage1_kernel(const float* __restrict__ x, const float* __restrict__ h,
              const float* __restrict__ m, const float* __restrict__ bx,
              const float* __restrict__ bh) {
    __shared__ __align__(16) float s_in[1020];
    __shared__ __align__(16) float s_w[1728];
    const int b = blockIdx.z & 7, k = blockIdx.z >> 3;
    const int t0 = blockIdx.y, wbase = blockIdx.x * 8;
    unsigned long long acc[2][8];
#pragma unroll
    for (int e = 0; e < 2; ++e)
#pragma unroll
        for (int p = 0; p < 8; ++p) acc[e][p] = 0ull;

    conv_accum512(x + (size_t)b * 16 * SP, g_wxT + k * 27648, 16, t0, wbase, s_in, s_w, acc);
    const float* st = (k < 3 || k == 6) ? h : m;
    conv_accum512(st + (size_t)b * CSP, g_whT + k * 110592, 64, t0, wbase, s_in, s_w, acc);

    const int tid = threadIdx.x;
    const int slot = tid & 127, hh = slot & 31, w0 = (slot >> 5) * 2, coq = tid >> 7;
    float* up = g_u + (size_t)k * VOL + (size_t)b * CSP + t0 * 1024 + hh;
#pragma unroll
    for (int e = 0; e < 2; ++e) {
        int row = (wbase + w0 + e) * 32;
#pragma unroll
        for (int p = 0; p < 8; ++p) {
            float lo, hi; unpack2(acc[e][p], lo, hi);
            int co = coq * 16 + 2 * p;
            up[(size_t)co * SP + row]       = lo + bx[k * 64 + co]     + bh[k * 64 + co];
            up[(size_t)(co + 1) * SP + row] = hi + bx[k * 64 + co + 1] + bh[k * 64 + co + 1];
        }
    }
}

// ---------------------------------------------------------------------------
// LN3 (per (b,co) over 4096) + activation in place; k in {2,4} -> tanh
// ---------------------------------------------------------------------------
__global__ void ln3_act_kernel(int kbase) {
    __shared__ float sh[32];
    const int k = kbase + blockIdx.y;
    float* buf = g_u + (size_t)k * VOL + (size_t)blockIdx.x * SP;
    const int tid = threadIdx.x;
    float v[16], s = 0.f, sq = 0.f;
#pragma unroll
    for (int j = 0; j < 16; ++j) {
        v[j] = buf[tid + j * 256];
        s += v[j]; sq += v[j] * v[j];
    }
    block_reduce2(s, sq, sh);
    const float mu = s * (1.f / 4096.f);
    const float var = sq * (1.f / 4096.f) - mu * mu;
    const float rstd = rsqrtf(var + EPSF);
    const bool ist = (k == 2 || k == 4);
#pragma unroll
    for (int j = 0; j < 16; ++j) {
        float y = (v[j] - mu) * rstd;
        buf[tid + j * 256] = ist ? tanhf(y) : (1.f / (1.f + expf(-y)));
    }
}

// ---------------------------------------------------------------------------
// attention: partial dot(r[b], c_history[l,b]) over 16 chunks per (l,b)
// ---------------------------------------------------------------------------
__global__ void scores_part_kernel(const float* __restrict__ ch) {
    __shared__ float sh[32];
    const int lb = blockIdx.x >> 4, chunk = blockIdx.x & 15;
    const int b = lb & 7;
    const float4* r4 = (const float4*)(g_u + (size_t)b * CSP) + chunk * 4096;
    const float4* c4 = (const float4*)(ch + (size_t)lb * CSP) + chunk * 4096;
    float s = 0.f;
    for (int i = threadIdx.x; i < 4096; i += 256) {
        float4 a = r4[i], c = c4[i];
        s += a.x * c.x + a.y * c.y + a.z * c.z + a.w * c.w;
    }
    float d = 0.f;
    block_reduce2(s, d, sh);
    if (threadIdx.x == 0) g_spart[blockIdx.x] = s;
}

// reduce partials -> scores[l][b] -> softmax over b per l (faithful to source)
__global__ void scores_softmax_kernel() {
    __shared__ float ssc[40];
    const int t = threadIdx.x;
    if (t < 40) {
        float s = 0.f;
        for (int j = 0; j < 16; ++j) s += g_spart[t * 16 + j];
        ssc[t] = s * (1.f / 64.f);
    }
    __syncthreads();
    if (t < 5) {
        const int l = t;
        float mx = -1e30f;
        for (int b = 0; b < 8; ++b) mx = fmaxf(mx, ssc[l * 8 + b]);
        float e[8], sum = 0.f;
        for (int b = 0; b < 8; ++b) { e[b] = expf(ssc[l * 8 + b] - mx); sum += e[b]; }
        float inv = 1.f / sum;
        for (int b = 0; b < 8; ++b) g_attn[l * 8 + b] = e[b] * inv;
    }
}

// ---------------------------------------------------------------------------
// z = c_history[4] + recall; write to out c-slot; LN4 partial stats
// ---------------------------------------------------------------------------
__global__ void zstats_kernel(const float* __restrict__ ch, float* __restrict__ out) {
    __shared__ float sh[32];
    const int b = blockIdx.x >> 8;
    const int off = (blockIdx.x & 255) * 1024;
    const float a0 = g_attn[b],      a1 = g_attn[8 + b], a2 = g_attn[16 + b];
    const float a3 = g_attn[24 + b], a4 = 1.f + g_attn[32 + b];
    const float* c0 = ch + (size_t)b * CSP;
    float* zc = out + (size_t)4 * VOL + (size_t)b * CSP;
    float s = 0.f, sq = 0.f;
#pragma unroll
    for (int j = 0; j < 4; ++j) {
        int i = off + threadIdx.x + j * 256;
        float z = a0 * c0[i] + a1 * c0[i + VOL] + a2 * c0[i + 2 * VOL]
                + a3 * c0[i + 3 * VOL] + a4 * c0[i + 4 * VOL];
        zc[i] = z; s += z; sq += z * z;
    }
    block_reduce2(s, sq, sh);
    if (threadIdx.x == 0) { g_part[blockIdx.x * 2] = s; g_part[blockIdx.x * 2 + 1] = sq; }
}

__global__ void stats_reduce_kernel() {
    __shared__ float sh[32];
    const int b = blockIdx.x;
    float s  = g_part[(b * 256 + threadIdx.x) * 2];
    float sq = g_part[(b * 256 + threadIdx.x) * 2 + 1];
    block_reduce2(s, sq, sh);
    if (threadIdx.x == 0) { g_stats[b * 2] = s; g_stats[b * 2 + 1] = sq; }
}

// ---------------------------------------------------------------------------
// finalize: c = i*g + LN4(z)*lnw + lnb ; m_new = i'*g' + f'*m
// ---------------------------------------------------------------------------
__global__ void finalize_kernel(const float* __restrict__ m, const float* __restrict__ lnw,
                                const float* __restrict__ lnb, float* __restrict__ out) {
    const int base = blockIdx.x * 1024;
#pragma unroll
    for (int j = 0; j < 4; ++j) {
        int idx = base + threadIdx.x + j * 256;
        int b = idx >> 18;
        int cs = idx & (CSP - 1);
        float mu = g_stats[2 * b] * (1.f / (float)CSP);
        float var = g_stats[2 * b + 1] * (1.f / (float)CSP) - mu * mu;
        float rstd = rsqrtf(var + EPSF);
        float z = out[4 * VOL + idx];
        float c = g_u[1 * VOL + idx] * g_u[2 * VOL + idx]
                + (z - mu) * rstd * lnw[cs] + lnb[cs];
        float mn = g_u[3 * VOL + idx] * g_u[4 * VOL + idx]
                 + g_u[5 * VOL + idx] * m[idx];
        out[4 * VOL + idx] = c;
        out[5 * VOL + idx] = mn;
    }
}

// ---------------------------------------------------------------------------
// stage5: u6 += conv(c,Wh[7]) + conv(m_new,Wh[8]) + bh[7] + bh[8]
// ---------------------------------------------------------------------------
__global__ void __launch_bounds__(512, 1)
stage5_kernel(const float* __restrict__ out, const float* __restrict__ bh) {
    __shared__ __align__(16) float s_in[1020];
    __shared__ __align__(16) float s_w[1728];
    const int b = blockIdx.z, t0 = blockIdx.y, wbase = blockIdx.x * 8;
    unsigned long long acc[2][8];
#pragma unroll
    for (int e = 0; e < 2; ++e)
#pragma unroll
        for (int p = 0; p < 8; ++p) acc[e][p] = 0ull;

    conv_accum512(out + (size_t)4 * VOL + (size_t)b * CSP, g_whT + 7 * 110592, 64,
                  t0, wbase, s_in, s_w, acc);
    conv_accum512(out + (size_t)5 * VOL + (size_t)b * CSP, g_whT + 8 * 110592, 64,
                  t0, wbase, s_in, s_w, acc);

    const int tid = threadIdx.x;
    const int slot = tid & 127, hh = slot & 31, w0 = (slot >> 5) * 2, coq = tid >> 7;
    float* up = g_u + (size_t)6 * VOL + (size_t)b * CSP + t0 * 1024 + hh;
#pragma unroll
    for (int e = 0; e < 2; ++e) {
        int row = (wbase + w0 + e) * 32;
#pragma unroll
        for (int p = 0; p < 8; ++p) {
            float lo, hi; unpack2(acc[e][p], lo, hi);
            int co = coq * 16 + 2 * p;
            up[(size_t)co * SP + row]       += lo + bh[448 + co]     + bh[512 + co];
            up[(size_t)(co + 1) * SP + row] += hi + bh[448 + co + 1] + bh[512 + co + 1];
        }
    }
}

// ---------------------------------------------------------------------------
// stage7: h_new = o * tanh( w111 @ cat(c, m_new) + b111 )
// ---------------------------------------------------------------------------
__global__ void __launch_bounds__(256, 2)
stage7_kernel(float* __restrict__ out, const float* __restrict__ b111) {
    __shared__ __align__(16) float s_w[8192];     // [128 ci][64 co]
    const int b = blockIdx.z, t0 = blockIdx.y, wbase = blockIdx.x * 8;
    const int tid = threadIdx.x, wl = tid >> 5, hh = tid & 31;
    for (int idx = tid; idx < 2048; idx += 256)
        reinterpret_cast<float4*>(s_w)[idx] = reinterpret_cast<const float4*>(g_w111T)[idx];
    __syncthreads();

    const int pos = t0 * 1024 + (wbase + wl) * 32 + hh;
    const float* cb = out + (size_t)4 * VOL + (size_t)b * CSP + pos;
    const float* mb = out + (size_t)5 * VOL + (size_t)b * CSP + pos;
    unsigned long long acc[32];
#pragma unroll
    for (int i = 0; i < 32; ++i) acc[i] = 0ull;

    for (int half = 0; half < 2; ++half) {
        const float* src = half ? mb : cb;
        for (int ci0 = 0; ci0 < 64; ci0 += 8) {
            float v[8];
#pragma unroll
            for (int j = 0; j < 8; ++j) v[j] = src[(size_t)(ci0 + j) * SP];
#pragma unroll
            for (int j = 0; j < 8; ++j) {
                unsigned long long vv = bcast2(v[j]);
                const ulonglong2* wq = reinterpret_cast<const ulonglong2*>(
                    s_w + (half * 64 + ci0 + j) * 64);
#pragma unroll
                for (int q = 0; q < 16; ++q) {
                    ulonglong2 wp = wq[q];
                    ffma2(acc[2 * q], vv, wp.x);
                    ffma2(acc[2 * q + 1], vv, wp.y);
                }
            }
        }
    }

    const float* ob = g_u + (size_t)6 * VOL + (size_t)b * CSP + pos;
    float* hb = out + (size_t)6 * VOL + (size_t)b * CSP + pos;
#pragma unroll
    for (int cp = 0; cp < 32; ++cp) {
        float lo, hi; unpack2(acc[cp], lo, hi);
        int co = 2 * cp;
        hb[(size_t)co * SP]       = ob[(size_t)co * SP]       * tanhf(lo + b111[co]);
        hb[(size_t)(co + 1) * SP] = ob[(size_t)(co + 1) * SP] * tanhf(hi + b111[co + 1]);
    }
}

// ---------------------------------------------------------------------------
// host launcher
// ---------------------------------------------------------------------------
extern "C" void kernel_launch(void* const* d_in, const int* in_sizes, int n_in,
                              void* d_out, int out_size) {
    (void)in_sizes; (void)n_in; (void)out_size;
    const float* x    = (const float*)d_in[0];
    const float* ch   = (const float*)d_in[1];
    const float* m    = (const float*)d_in[2];
    const float* h    = (const float*)d_in[3];
    const float* Wx   = (const float*)d_in[4];
    const float* bx   = (const float*)d_in[5];
    const float* Wh   = (const float*)d_in[6];
    const float* bh   = (const float*)d_in[7];
    const float* w111 = (const float*)d_in[8];
    const float* b111 = (const float*)d_in[9];
    const float* lnw  = (const float*)d_in[10];
    const float* lnb  = (const float*)d_in[11];
    float* out = (float*)d_out;

    prep_kernel<<<4676, 256>>>(Wx, Wh, w111);
    stage1_kernel<<<dim3(4, 4, 56), 512>>>(x, h, m, bx, bh);     // u0..u6 pre-acts
    ln3_act_kernel<<<dim3(512, 6), 256>>>(0);                    // r,i,g,i',g',f'
    scores_part_kernel<<<640, 256>>>(ch);
    scores_softmax_kernel<<<1, 64>>>();
    zstats_kernel<<<2048, 256>>>(ch, out);                       // z + LN4 partials
    stats_reduce_kernel<<<8, 256>>>();
    finalize_kernel<<<2048, 256>>>(m, lnw, lnb, out);            // c, m_new
    stage5_kernel<<<dim3(4, 4, 8), 512>>>(out, bh);              // u6 += conv(c)+conv(m_new)
    ln3_act_kernel<<<dim3(512, 1), 256>>>(6);                    // o
    stage7_kernel<<<dim3(4, 4, 8), 256>>>(out, b111);            // h_new
    cudaMemcpyAsync(out, ch + VOL, (size_t)4 * VOL * sizeof(float),
                    cudaMemcpyDeviceToDevice);                   // c_history shift
}

// round 16
// speedup vs baseline: 5.6319x; 5.6319x over previous
#include <cuda_runtime.h>
#include <cuda_fp16.h>
#include <cstdint>

#define SP   4096
#define CSP  262144
#define VOL  2097152
#define EPSF 1e-5f
// CL images (fp16): states [dh3][b8][t4][1088 rows][64 ci]; plane = 1088*64
#define CL_PLANE 69632
#define CL_STATE (3 * 8 * 4 * CL_PLANE)

__device__ __half g_Hcl[CL_STATE];
__device__ __half g_Mcl[CL_STATE];
__device__ __half g_Ccl[CL_STATE];
__device__ __half g_MNcl[CL_STATE];
__device__ __half g_Xcl[8 * 4 * CL_PLANE];          // dh folded into K
__device__ __half g_whB[9 * 27 * 4096];             // [k][tap][64co x 64k swizzled]
__device__ __half g_wxB[7 * 9 * 4096];              // [k][dt*3+dw][64co x 64kk]
__device__ float g_w111T[128 * 64];
__device__ float g_u[7u * (unsigned)VOL];
__device__ float g_spart[640];
__device__ float g_attn[40];
__device__ float g_part[2048 * 2];
__device__ float g_stats[16];

// ---------------- helpers ----------------
__device__ __forceinline__ uint32_t smem_u32(const void* p) {
    uint32_t a;
    asm("{ .reg .u64 t; cvta.to.shared.u64 t, %1; cvt.u32.u64 %0, t; }" : "=r"(a) : "l"(p));
    return a;
}
__device__ __forceinline__ void ldm4(uint32_t r[4], uint32_t addr) {
    asm volatile("ldmatrix.sync.aligned.m8n8.x4.shared.b16 {%0,%1,%2,%3}, [%4];"
        : "=r"(r[0]), "=r"(r[1]), "=r"(r[2]), "=r"(r[3]) : "r"(addr));
}
__device__ __forceinline__ void mma16816(float d[4], const uint32_t a[4],
                                         uint32_t b0, uint32_t b1) {
    asm volatile("mma.sync.aligned.m16n8k16.row.col.f32.f16.f16.f32 "
        "{%0,%1,%2,%3}, {%4,%5,%6,%7}, {%8,%9}, {%0,%1,%2,%3};"
        : "+f"(d[0]), "+f"(d[1]), "+f"(d[2]), "+f"(d[3])
        : "r"(a[0]), "r"(a[1]), "r"(a[2]), "r"(a[3]), "r"(b0), "r"(b1));
}
__device__ __forceinline__ uint32_t packh2(float a, float b) {
    __half2 t = __floats2half2_rn(a, b);
    return *reinterpret_cast<uint32_t*>(&t);
}
__device__ __forceinline__ unsigned long long bcast2(float v) {
    unsigned long long r; asm("mov.b64 %0, {%1, %1};" : "=l"(r) : "f"(v)); return r;
}
__device__ __forceinline__ void ffma2(unsigned long long& a, unsigned long long v, unsigned long long w) {
    asm("fma.rn.f32x2 %0, %1, %2, %0;" : "+l"(a) : "l"(v), "l"(w));
}
__device__ __forceinline__ void unpack2(unsigned long long a, float& lo, float& hi) {
    asm("mov.b64 {%0, %1}, %2;" : "=f"(lo), "=f"(hi) : "l"(a));
}
__device__ __forceinline__ void block_reduce2(float& a, float& b, float* sh) {
    const int lane = threadIdx.x & 31, wid = threadIdx.x >> 5;
    const int nw = blockDim.x >> 5;
#pragma unroll
    for (int o = 16; o; o >>= 1) {
        a += __shfl_down_sync(0xffffffffu, a, o);
        b += __shfl_down_sync(0xffffffffu, b, o);
    }
    if (lane == 0) { sh[wid] = a; sh[16 + wid] = b; }
    __syncthreads();
    if (wid == 0) {
        a = lane < nw ? sh[lane] : 0.f;
        b = lane < nw ? sh[16 + lane] : 0.f;
#pragma unroll
        for (int o = 8; o; o >>= 1) {
            a += __shfl_down_sync(0xffffffffu, a, o);
            b += __shfl_down_sync(0xffffffffu, b, o);
        }
        if (lane == 0) { sh[0] = a; sh[16] = b; }
    }
    __syncthreads();
    a = sh[0]; b = sh[16];
}

// ---------------- prep: fp16 weight images, 16B-group XOR swizzle ----------------
__global__ void prep_kernel(const float* __restrict__ Wx, const float* __restrict__ Wh,
                            const float* __restrict__ w111) {
    int idx = blockIdx.x * 256 + threadIdx.x;
    if (idx < 995328) {                       // Wh: (k,tap,co,ci)
        int ci = idx & 63, co = (idx >> 6) & 63;
        int tap = (idx >> 12) % 27, k = (idx >> 12) / 27;
        float v = Wh[((k * 64 + co) * 64 + ci) * 27 + tap];
        g_whB[(k * 27 + tap) * 4096 + co * 64 + (ci ^ ((co & 7) << 3))] = __float2half_rn(v);
    } else if (idx < 1253376) {               // Wx: (k,dt,dw,co,kk) kk=dh*16+ci
        int j = idx - 995328;
        int kk = j & 63, co = (j >> 6) & 63;
        int r = j >> 12;
        int dw = r % 3, dt = (r / 3) % 3, k = r / 9;
        int dh = kk >> 4, ci = kk & 15;
        float v = (kk < 48) ? Wx[((k * 64 + co) * 16 + ci) * 27 + dt * 9 + dw * 3 + dh] : 0.f;
        g_wxB[(k * 9 + dt * 3 + dw) * 4096 + co * 64 + (kk ^ ((co & 7) << 3))] = __float2half_rn(v);
    } else if (idx < 1261568) {               // w111 -> [ci][co]
        int j = idx - 1253376;
        g_w111T[j] = w111[(j & 63) * 128 + (j >> 6)];
    }
}

// ---------------- state -> CL fp16, 3 dh shifts, swizzled ----------------
__global__ void convert_state_kernel(const float* __restrict__ src, int sel) {
    __shared__ float s[64][33];
    __half* dst = sel == 0 ? g_Hcl : sel == 1 ? g_Mcl : sel == 2 ? g_Ccl : g_MNcl;
    const int wp = blockIdx.x, t = blockIdx.y, b = blockIdx.z;
    const int w = wp - 1;
    const bool valid = ((unsigned)w < 32u);
    if (valid) {
        int ci8 = threadIdx.x >> 5, hh = threadIdx.x & 31;
#pragma unroll
        for (int j = 0; j < 8; ++j) {
            int ci = ci8 * 8 + j;
            s[ci][hh] = src[(size_t)b * CSP + (size_t)ci * SP + t * 1024 + w * 32 + hh];
        }
    }
    __syncthreads();
    const int row = threadIdx.x >> 3, grp = threadIdx.x & 7, key = row & 7;
    const size_t rowoff = (size_t)(wp * 32 + row) * 64;
#pragma unroll
    for (int dh = 0; dh < 3; ++dh) {
        int hs = row + dh - 1;
        bool ok = valid && ((unsigned)hs < 32u);
        uint4 u;
        uint32_t* pu = &u.x;
#pragma unroll
        for (int q = 0; q < 4; ++q) {
            int ci0 = grp * 8 + 2 * q;
            pu[q] = packh2(ok ? s[ci0][hs] : 0.f, ok ? s[ci0 + 1][hs] : 0.f);
        }
        size_t p = ((size_t)(dh * 8 + b) * 4 + t) * CL_PLANE + rowoff;
        reinterpret_cast<uint4*>(dst + p)[grp ^ key] = u;
    }
}

__global__ void convert_x_kernel(const float* __restrict__ x) {
    __shared__ float s[16][33];
    const int wp = blockIdx.x, t = blockIdx.y, b = blockIdx.z;
    const int w = wp - 1;
    const bool valid = ((unsigned)w < 32u);
    if (valid)
        for (int idx = threadIdx.x; idx < 512; idx += 256) {
            int ci = idx >> 5, hh = idx & 31;
            s[ci][hh] = x[(size_t)b * 16 * SP + (size_t)ci * SP + t * 1024 + w * 32 + hh];
        }
    __syncthreads();
    const int row = threadIdx.x >> 3, grp = threadIdx.x & 7, key = row & 7;
    uint4 u;
    uint32_t* pu = &u.x;
#pragma unroll
    for (int q = 0; q < 4; ++q) {
        float v[2];
#pragma unroll
        for (int e = 0; e < 2; ++e) {
            int kk = grp * 8 + 2 * q + e;
            int dh = kk >> 4, ci = kk & 15, hs = row + dh - 1;
            v[e] = (valid && kk < 48 && (unsigned)hs < 32u) ? s[ci][hs] : 0.f;
        }
        pu[q] = packh2(v[0], v[1]);
    }
    size_t p = ((size_t)b * 4 + t) * CL_PLANE + (size_t)(wp * 32 + row) * 64;
    reinterpret_cast<uint4*>(g_Xcl + p)[grp ^ key] = u;
}

// ---------------- HMMA implicit-GEMM conv ----------------
// Block: 256 rows x 64 co; 8 warps = 4 rowgroups(64) x 2 cohalves(32).
// mode 0: grid (4 wq, 4 t, 56=k*8+b): u_k = conv(x)+conv(h|m)+biases
// mode 1: grid (4, 4, 8):             u6 += conv(c,Wh7)+conv(mn,Wh8)+bh7+bh8
// Dyn smem: [1024 pad][A: 320 rows x 128B = 40960][B: 3 x 8192 = 24576] = 66560
#define OFF_A 1024
#define OFF_B 41984
#define DSMEM 66560

__global__ void __launch_bounds__(256, 2)
conv_mma_kernel(int mode, const float* __restrict__ bx, const float* __restrict__ bh) {
    extern __shared__ char smem[];
    const uint32_t sb = smem_u32(smem);
    const int tid = threadIdx.x, warp = tid >> 5, lane = tid & 31;
    const int wq = blockIdx.x, t0 = blockIdx.y;
    int b, k;
    if (mode == 0) { b = blockIdx.z & 7; k = blockIdx.z >> 3; }
    else           { b = blockIdx.z;     k = 6; }
    const int rg = warp & 3;                  // row group (64 rows)
    const int cbase = (warp >> 2) * 32;       // co half base

    // lane constants (A and B ldmatrix addressing)
    const int rA  = (lane & 7) + ((lane >> 3) & 1) * 8;   // row within 16-tile
    const int kgA = lane >> 4;                            // k 16B-group (0/1)
    const int nB  = (lane & 7) + ((lane >> 4) & 1) * 8;   // n within ntile pair
    const int kgB = (lane >> 3) & 1;
    const uint32_t sA = sb + OFF_A, sBB = sb + OFF_B;

    float acc[4][4][4];                       // [rowtile][ntile][4]
#pragma unroll
    for (int i = 0; i < 4; ++i)
#pragma unroll
        for (int j = 0; j < 4; ++j)
#pragma unroll
            for (int q = 0; q < 4; ++q) acc[i][j][q] = 0.f;

    for (int src = 0; src < 2; ++src) {
        const __half* acl;
        const __half* wb;
        int ndh, nch;
        if (mode == 0) {
            if (src == 0) { acl = (k < 3 || k == 6) ? g_Hcl : g_Mcl;
                            wb = g_whB + (size_t)k * 27 * 4096; ndh = 3; nch = 4; }
            else          { acl = g_Xcl; wb = g_wxB + (size_t)k * 9 * 4096; ndh = 1; nch = 3; }
        } else {
            acl = src ? g_MNcl : g_Ccl;
            wb = g_whB + (size_t)(7 + src) * 27 * 4096; ndh = 3; nch = 4;
        }
        for (int dt = 0; dt < 3; ++dt) {
            int t = t0 + dt - 1;
            if ((unsigned)t >= 4u) continue;
            for (int dh = 0; dh < ndh; ++dh) {
                __syncthreads();              // prior MMA reads done before refill
                // A fill: 320 rows x 128B (contiguous)
                {
                    size_t plane = (mode == 0 && src == 1)
                        ? ((size_t)b * 4 + t) * CL_PLANE
                        : ((size_t)(dh * 8 + b) * 4 + t) * CL_PLANE;
                    const uint4* s4 = reinterpret_cast<const uint4*>(acl + plane + (size_t)wq * 256 * 64);
                    uint4* d4 = reinterpret_cast<uint4*>(smem + OFF_A);
#pragma unroll
                    for (int i = 0; i < 10; ++i) d4[tid + i * 256] = s4[tid + i * 256];
                }
                // B fill: 3 dw images x 8KB
                {
                    uint4* d4 = reinterpret_cast<uint4*>(smem + OFF_B);
#pragma unroll
                    for (int i = 0; i < 6; ++i) {
                        int j = tid + i * 256;
                        int dw = j >> 9, off = j & 511;
                        const uint4* s4 = (mode == 0 && src == 1)
                            ? reinterpret_cast<const uint4*>(wb + (size_t)(dt * 3 + dw) * 4096)
                            : reinterpret_cast<const uint4*>(wb + (size_t)(dt * 9 + dw * 3 + dh) * 4096);
                        d4[j] = s4[off];
                    }
                }
                __syncthreads();
#pragma unroll
                for (int dw = 0; dw < 3; ++dw) {
                    for (int c = 0; c < nch; ++c) {
                        uint32_t bfr[4][2];
#pragma unroll
                        for (int ntp = 0; ntp < 2; ++ntp) {
                            int corow = cbase + ntp * 16 + nB;
                            uint32_t addr = sBB + dw * 8192 + corow * 128
                                          + (((2 * c + kgB) ^ (corow & 7)) << 4);
                            uint32_t rr[4];
                            ldm4(rr, addr);
                            bfr[ntp * 2][0] = rr[0]; bfr[ntp * 2][1] = rr[1];
                            bfr[ntp * 2 + 1][0] = rr[2]; bfr[ntp * 2 + 1][1] = rr[3];
                        }
#pragma unroll
                        for (int rt = 0; rt < 4; ++rt) {
                            int row = rg * 64 + rt * 16 + rA + dw * 32;
                            uint32_t addr = sA + row * 128
                                          + (((2 * c + kgA) ^ (lane & 7)) << 4);
                            uint32_t afr[4];
                            ldm4(afr, addr);
#pragma unroll
                            for (int nt = 0; nt < 4; ++nt)
                                mma16816(acc[rt][nt], afr, bfr[nt][0], bfr[nt][1]);
                        }
                    }
                }
            }
        }
    }

    // epilogue: stage D in smem (XOR pad), then coalesced [co][spatial] writes
    __syncthreads();
    float* so = reinterpret_cast<float*>(smem + 1024);   // [64 co][256 rows]
#pragma unroll
    for (int rt = 0; rt < 4; ++rt)
#pragma unroll
        for (int nt = 0; nt < 4; ++nt) {
            int row0 = rg * 64 + rt * 16 + (lane >> 2);
            int co0 = cbase + nt * 8 + (lane & 3) * 2;
            so[co0 * 256 + (row0 ^ ((co0 & 7) << 2))] = acc[rt][nt][0];
            so[(co0 + 1) * 256 + (row0 ^ (((co0 + 1) & 7) << 2))] = acc[rt][nt][1];
            int row1 = row0 + 8;
            so[co0 * 256 + (row1 ^ ((co0 & 7) << 2))] = acc[rt][nt][2];
            so[(co0 + 1) * 256 + (row1 ^ (((co0 + 1) & 7) << 2))] = acc[rt][nt][3];
        }
    __syncthreads();
#pragma unroll
    for (int ci = 0; ci < 8; ++ci) {
        int co = warp * 8 + ci;
        float bias = (mode == 0) ? (bx[k * 64 + co] + bh[k * 64 + co])
                                 : (bh[448 + co] + bh[512 + co]);
        float* up = g_u + (size_t)k * VOL + (size_t)b * CSP + (size_t)co * SP
                  + t0 * 1024 + wq * 256;
        const int xr = (co & 7) << 2;
#pragma unroll
        for (int j = 0; j < 8; ++j) {
            int row = lane + 32 * j;
            float v = so[co * 256 + (row ^ xr)] + bias;
            if (mode == 0) up[row] = v; else up[row] += v;
        }
    }
}

// ---------------- LN3 + act ----------------
__global__ void ln3_act_kernel(int kbase) {
    __shared__ float sh[32];
    const int k = kbase + blockIdx.y;
    float* buf = g_u + (size_t)k * VOL + (size_t)blockIdx.x * SP;
    const int tid = threadIdx.x;
    float v[16], s = 0.f, sq = 0.f;
#pragma unroll
    for (int j = 0; j < 16; ++j) {
        v[j] = buf[tid + j * 256];
        s += v[j]; sq += v[j] * v[j];
    }
    block_reduce2(s, sq, sh);
    const float mu = s * (1.f / 4096.f);
    const float var = sq * (1.f / 4096.f) - mu * mu;
    const float rstd = rsqrtf(var + EPSF);
    const bool ist = (k == 2 || k == 4);
#pragma unroll
    for (int j = 0; j < 16; ++j) {
        float y = (v[j] - mu) * rstd;
        buf[tid + j * 256] = ist ? tanhf(y) : (1.f / (1.f + expf(-y)));
    }
}

__global__ void scores_part_kernel(const float* __restrict__ ch) {
    __shared__ float sh[32];
    const int lb = blockIdx.x >> 4, chunk = blockIdx.x & 15;
    const int b = lb & 7;
    const float4* r4 = (const float4*)(g_u + (size_t)b * CSP) + chunk * 4096;
    const float4* c4 = (const float4*)(ch + (size_t)lb * CSP) + chunk * 4096;
    float s = 0.f;
    for (int i = threadIdx.x; i < 4096; i += 256) {
        float4 a = r4[i], c = c4[i];
        s += a.x * c.x + a.y * c.y + a.z * c.z + a.w * c.w;
    }
    float d = 0.f;
    block_reduce2(s, d, sh);
    if (threadIdx.x == 0) g_spart[blockIdx.x] = s;
}

__global__ void scores_softmax_kernel() {
    __shared__ float ssc[40];
    const int t = threadIdx.x;
    if (t < 40) {
        float s = 0.f;
        for (int j = 0; j < 16; ++j) s += g_spart[t * 16 + j];
        ssc[t] = s * (1.f / 64.f);
    }
    __syncthreads();
    if (t < 5) {
        const int l = t;
        float mx = -1e30f;
        for (int b = 0; b < 8; ++b) mx = fmaxf(mx, ssc[l * 8 + b]);
        float e[8], sum = 0.f;
        for (int b = 0; b < 8; ++b) { e[b] = expf(ssc[l * 8 + b] - mx); sum += e[b]; }
        float inv = 1.f / sum;
        for (int b = 0; b < 8; ++b) g_attn[l * 8 + b] = e[b] * inv;
    }
}

__global__ void zstats_kernel(const float* __restrict__ ch, float* __restrict__ out) {
    __shared__ float sh[32];
    const int b = blockIdx.x >> 8;
    const int off = (blockIdx.x & 255) * 1024;
    const float a0 = g_attn[b],      a1 = g_attn[8 + b], a2 = g_attn[16 + b];
    const float a3 = g_attn[24 + b], a4 = 1.f + g_attn[32 + b];
    const float* c0 = ch + (size_t)b * CSP;
    float* zc = out + (size_t)4 * VOL + (size_t)b * CSP;
    float s = 0.f, sq = 0.f;
#pragma unroll
    for (int j = 0; j < 4; ++j) {
        int i = off + threadIdx.x + j * 256;
        float z = a0 * c0[i] + a1 * c0[i + VOL] + a2 * c0[i + 2 * VOL]
                + a3 * c0[i + 3 * VOL] + a4 * c0[i + 4 * VOL];
        zc[i] = z; s += z; sq += z * z;
    }
    block_reduce2(s, sq, sh);
    if (threadIdx.x == 0) { g_part[blockIdx.x * 2] = s; g_part[blockIdx.x * 2 + 1] = sq; }
}

__global__ void stats_reduce_kernel() {
    __shared__ float sh[32];
    const int b = blockIdx.x;
    float s  = g_part[(b * 256 + threadIdx.x) * 2];
    float sq = g_part[(b * 256 + threadIdx.x) * 2 + 1];
    block_reduce2(s, sq, sh);
    if (threadIdx.x == 0) { g_stats[b * 2] = s; g_stats[b * 2 + 1] = sq; }
}

__global__ void finalize_kernel(const float* __restrict__ m, const float* __restrict__ lnw,
                                const float* __restrict__ lnb, float* __restrict__ out) {
    const int base = blockIdx.x * 1024;
#pragma unroll
    for (int j = 0; j < 4; ++j) {
        int idx = base + threadIdx.x + j * 256;
        int b = idx >> 18;
        int cs = idx & (CSP - 1);
        float mu = g_stats[2 * b] * (1.f / (float)CSP);
        float var = g_stats[2 * b + 1] * (1.f / (float)CSP) - mu * mu;
        float rstd = rsqrtf(var + EPSF);
        float z = out[4 * VOL + idx];
        float c = g_u[1 * VOL + idx] * g_u[2 * VOL + idx] + (z - mu) * rstd * lnw[cs] + lnb[cs];
        float mn = g_u[3 * VOL + idx] * g_u[4 * VOL + idx] + g_u[5 * VOL + idx] * m[idx];
        out[4 * VOL + idx] = c;
        out[5 * VOL + idx] = mn;
    }
}

// ---------------- stage7 (FFMA2 GEMM) ----------------
__global__ void __launch_bounds__(256, 2)
stage7_kernel(float* __restrict__ out, const float* __restrict__ b111) {
    __shared__ __align__(16) float s_w[8192];
    const int b = blockIdx.z, t0 = blockIdx.y, wbase = blockIdx.x * 8;
    const int tid = threadIdx.x, wl = tid >> 5, hh = tid & 31;
    for (int idx = tid; idx < 2048; idx += 256)
        reinterpret_cast<float4*>(s_w)[idx] = reinterpret_cast<const float4*>(g_w111T)[idx];
    __syncthreads();
    const int pos = t0 * 1024 + (wbase + wl) * 32 + hh;
    const float* cb = out + (size_t)4 * VOL + (size_t)b * CSP + pos;
    const float* mb = out + (size_t)5 * VOL + (size_t)b * CSP + pos;
    unsigned long long acc[32];
#pragma unroll
    for (int i = 0; i < 32; ++i) acc[i] = 0ull;
    for (int half = 0; half < 2; ++half) {
        const float* src = half ? mb : cb;
        for (int ci0 = 0; ci0 < 64; ci0 += 8) {
            float v[8];
#pragma unroll
            for (int j = 0; j < 8; ++j) v[j] = src[(size_t)(ci0 + j) * SP];
#pragma unroll
            for (int j = 0; j < 8; ++j) {
                unsigned long long vv = bcast2(v[j]);
                const ulonglong2* wq = reinterpret_cast<const ulonglong2*>(
                    s_w + (half * 64 + ci0 + j) * 64);
#pragma unroll
                for (int q = 0; q < 16; ++q) {
                    ulonglong2 wp = wq[q];
                    ffma2(acc[2 * q], vv, wp.x);
                    ffma2(acc[2 * q + 1], vv, wp.y);
                }
            }
        }
    }
    const float* ob = g_u + (size_t)6 * VOL + (size_t)b * CSP + pos;
    float* hb = out + (size_t)6 * VOL + (size_t)b * CSP + pos;
#pragma unroll
    for (int cp = 0; cp < 32; ++cp) {
        float lo, hi; unpack2(acc[cp], lo, hi);
        int co = 2 * cp;
        hb[(size_t)co * SP]       = ob[(size_t)co * SP]       * tanhf(lo + b111[co]);
        hb[(size_t)(co + 1) * SP] = ob[(size_t)(co + 1) * SP] * tanhf(hi + b111[co + 1]);
    }
}

// ---------------- host ----------------
extern "C" void kernel_launch(void* const* d_in, const int* in_sizes, int n_in,
                              void* d_out, int out_size) {
    (void)in_sizes; (void)n_in; (void)out_size;
    const float* x    = (const float*)d_in[0];
    const float* ch   = (const float*)d_in[1];
    const float* m    = (const float*)d_in[2];
    const float* h    = (const float*)d_in[3];
    const float* Wx   = (const float*)d_in[4];
    const float* bx   = (const float*)d_in[5];
    const float* Wh   = (const float*)d_in[6];
    const float* bh   = (const float*)d_in[7];
    const float* w111 = (const float*)d_in[8];
    const float* b111 = (const float*)d_in[9];
    const float* lnw  = (const float*)d_in[10];
    const float* lnb  = (const float*)d_in[11];
    float* out = (float*)d_out;

    // Immediate (non-stream) API; runs on the pre-capture correctness call too,
    // so the attribute is already set process-wide before graph capture.
    cudaFuncSetAttribute(conv_mma_kernel, cudaFuncAttributeMaxDynamicSharedMemorySize, DSMEM);

    prep_kernel<<<4928, 256>>>(Wx, Wh, w111);
    convert_x_kernel<<<dim3(34, 4, 8), 256>>>(x);
    convert_state_kernel<<<dim3(34, 4, 8), 256>>>(h, 0);
    convert_state_kernel<<<dim3(34, 4, 8), 256>>>(m, 1);
    conv_mma_kernel<<<dim3(4, 4, 56), 256, DSMEM>>>(0, bx, bh);   // u0..u6 pre-acts
    ln3_act_kernel<<<dim3(512, 6), 256>>>(0);                     // r,i,g,i',g',f'
    scores_part_kernel<<<640, 256>>>(ch);
    scores_softmax_kernel<<<1, 64>>>();
    zstats_kernel<<<2048, 256>>>(ch, out);
    stats_reduce_kernel<<<8, 256>>>();
    finalize_kernel<<<2048, 256>>>(m, lnw, lnb, out);             // c, m_new
    convert_state_kernel<<<dim3(34, 4, 8), 256>>>(out + (size_t)4 * VOL, 2);
    convert_state_kernel<<<dim3(34, 4, 8), 256>>>(out + (size_t)5 * VOL, 3);
    conv_mma_kernel<<<dim3(4, 4, 8), 256, DSMEM>>>(1, bx, bh);    // u6 += convs
    ln3_act_kernel<<<dim3(512, 1), 256>>>(6);                     // o
    stage7_kernel<<<dim3(4, 4, 8), 256>>>(out, b111);             // h_new
    cudaMemcpyAsync(out, ch + VOL, (size_t)4 * VOL * sizeof(float),
                    cudaMemcpyDeviceToDevice);                    // history shift
}

// round 17
// speedup vs baseline: 6.3520x; 1.1279x over previous
#include <cuda_runtime.h>
#include <cuda_fp16.h>
#include <cstdint>

#define SP   4096
#define CSP  262144
#define VOL  2097152
#define EPSF 1e-5f
// CL images (fp16): states [dh3][b8][t4][1088 rows][64 ci]; plane = 1088*64
#define CL_PLANE 69632
#define CL_STATE (3 * 8 * 4 * CL_PLANE)

__device__ __half g_Hcl[CL_STATE];
__device__ __half g_Mcl[CL_STATE];
__device__ __half g_Ccl[CL_STATE];
__device__ __half g_MNcl[CL_STATE];
__device__ __half g_Xcl[8 * 4 * CL_PLANE];          // dh folded into K
__device__ __half g_whB[9 * 27 * 4096];             // [k][dt][dh][dw][4096] (dw contiguous)
__device__ __half g_wxB[7 * 9 * 4096];              // [k][dt][dw][4096]
__device__ float g_w111T[128 * 64];
__device__ float g_u[7u * (unsigned)VOL];
__device__ float g_spart[640];
__device__ float g_attn[40];
__device__ float g_part[2048 * 2];
__device__ float g_stats[16];

// ---------------- helpers ----------------
__device__ __forceinline__ uint32_t smem_u32(const void* p) {
    uint32_t a;
    asm("{ .reg .u64 t; cvta.to.shared.u64 t, %1; cvt.u32.u64 %0, t; }" : "=r"(a) : "l"(p));
    return a;
}
__device__ __forceinline__ void ldm4(uint32_t r[4], uint32_t addr) {
    asm volatile("ldmatrix.sync.aligned.m8n8.x4.shared.b16 {%0,%1,%2,%3}, [%4];"
        : "=r"(r[0]), "=r"(r[1]), "=r"(r[2]), "=r"(r[3]) : "r"(addr));
}
__device__ __forceinline__ void mma16816(float d[4], const uint32_t a[4],
                                         uint32_t b0, uint32_t b1) {
    asm volatile("mma.sync.aligned.m16n8k16.row.col.f32.f16.f16.f32 "
        "{%0,%1,%2,%3}, {%4,%5,%6,%7}, {%8,%9}, {%0,%1,%2,%3};"
        : "+f"(d[0]), "+f"(d[1]), "+f"(d[2]), "+f"(d[3])
        : "r"(a[0]), "r"(a[1]), "r"(a[2]), "r"(a[3]), "r"(b0), "r"(b1));
}
__device__ __forceinline__ void mbar_wait(uint32_t mbar, uint32_t parity) {
    uint32_t done;
    asm volatile("{\n\t.reg .pred p;\n\t"
        "mbarrier.try_wait.parity.acquire.cta.shared::cta.b64 p, [%1], %2;\n\t"
        "selp.b32 %0, 1, 0, p;\n\t}" : "=r"(done) : "r"(mbar), "r"(parity) : "memory");
    if (!done)
        asm volatile("{\n\t.reg .pred P1;\n\tWL%=:\n\t"
            "mbarrier.try_wait.parity.acquire.cta.shared::cta.b64 P1, [%0], %1, 0x989680;\n\t"
            "@P1 bra.uni WD%=;\n\tbra.uni WL%=;\n\tWD%=:\n\t}"
            :: "r"(mbar), "r"(parity) : "memory");
}
__device__ __forceinline__ uint32_t packh2(float a, float b) {
    __half2 t = __floats2half2_rn(a, b);
    return *reinterpret_cast<uint32_t*>(&t);
}
__device__ __forceinline__ unsigned long long bcast2(float v) {
    unsigned long long r; asm("mov.b64 %0, {%1, %1};" : "=l"(r) : "f"(v)); return r;
}
__device__ __forceinline__ void ffma2(unsigned long long& a, unsigned long long v, unsigned long long w) {
    asm("fma.rn.f32x2 %0, %1, %2, %0;" : "+l"(a) : "l"(v), "l"(w));
}
__device__ __forceinline__ void unpack2(unsigned long long a, float& lo, float& hi) {
    asm("mov.b64 {%0, %1}, %2;" : "=f"(lo), "=f"(hi) : "l"(a));
}
__device__ __forceinline__ void block_reduce2(float& a, float& b, float* sh) {
    const int lane = threadIdx.x & 31, wid = threadIdx.x >> 5;
    const int nw = blockDim.x >> 5;
#pragma unroll
    for (int o = 16; o; o >>= 1) {
        a += __shfl_down_sync(0xffffffffu, a, o);
        b += __shfl_down_sync(0xffffffffu, b, o);
    }
    if (lane == 0) { sh[wid] = a; sh[16 + wid] = b; }
    __syncthreads();
    if (wid == 0) {
        a = lane < nw ? sh[lane] : 0.f;
        b = lane < nw ? sh[16 + lane] : 0.f;
#pragma unroll
        for (int o = 8; o; o >>= 1) {
            a += __shfl_down_sync(0xffffffffu, a, o);
            b += __shfl_down_sync(0xffffffffu, b, o);
        }
        if (lane == 0) { sh[0] = a; sh[16] = b; }
    }
    __syncthreads();
    a = sh[0]; b = sh[16];
}

// ---------------- prep: fp16 weight images, 16B-group XOR swizzle ----------------
__global__ void prep_kernel(const float* __restrict__ Wx, const float* __restrict__ Wh,
                            const float* __restrict__ w111) {
    int idx = blockIdx.x * 256 + threadIdx.x;
    if (idx < 995328) {                       // Wh: (k,tap,co,ci) -> [k][dt][dh][dw]
        int ci = idx & 63, co = (idx >> 6) & 63;
        int tap = (idx >> 12) % 27, k = (idx >> 12) / 27;
        int dt = tap / 9, dw = (tap % 9) / 3, dh = tap % 3;
        float v = Wh[((k * 64 + co) * 64 + ci) * 27 + tap];
        int base = (((k * 3 + dt) * 3 + dh) * 3 + dw) * 4096;
        g_whB[base + co * 64 + (ci ^ ((co & 7) << 3))] = __float2half_rn(v);
    } else if (idx < 1253376) {               // Wx: (k,dt,dw,co,kk) kk=dh*16+ci
        int j = idx - 995328;
        int kk = j & 63, co = (j >> 6) & 63;
        int r = j >> 12;
        int dw = r % 3, dt = (r / 3) % 3, k = r / 9;
        int dh = kk >> 4, ci = kk & 15;
        float v = (kk < 48) ? Wx[((k * 64 + co) * 16 + ci) * 27 + dt * 9 + dw * 3 + dh] : 0.f;
        g_wxB[(k * 9 + dt * 3 + dw) * 4096 + co * 64 + (kk ^ ((co & 7) << 3))] = __float2half_rn(v);
    } else if (idx < 1261568) {               // w111 -> [ci][co]
        int j = idx - 1253376;
        g_w111T[j] = w111[(j & 63) * 128 + (j >> 6)];
    }
}

// ---------------- state -> CL fp16, 3 dh shifts, swizzled ----------------
__global__ void convert_state_kernel(const float* __restrict__ src, int sel) {
    __shared__ float s[64][33];
    __half* dst = sel == 0 ? g_Hcl : sel == 1 ? g_Mcl : sel == 2 ? g_Ccl : g_MNcl;
    const int wp = blockIdx.x, t = blockIdx.y, b = blockIdx.z;
    const int w = wp - 1;
    const bool valid = ((unsigned)w < 32u);
    if (valid) {
        int ci8 = threadIdx.x >> 5, hh = threadIdx.x & 31;
#pragma unroll
        for (int j = 0; j < 8; ++j) {
            int ci = ci8 * 8 + j;
            s[ci][hh] = src[(size_t)b * CSP + (size_t)ci * SP + t * 1024 + w * 32 + hh];
        }
    }
    __syncthreads();
    const int row = threadIdx.x >> 3, grp = threadIdx.x & 7, key = row & 7;
    const size_t rowoff = (size_t)(wp * 32 + row) * 64;
#pragma unroll
    for (int dh = 0; dh < 3; ++dh) {
        int hs = row + dh - 1;
        bool ok = valid && ((unsigned)hs < 32u);
        uint4 u;
        uint32_t* pu = &u.x;
#pragma unroll
        for (int q = 0; q < 4; ++q) {
            int ci0 = grp * 8 + 2 * q;
            pu[q] = packh2(ok ? s[ci0][hs] : 0.f, ok ? s[ci0 + 1][hs] : 0.f);
        }
        size_t p = ((size_t)(dh * 8 + b) * 4 + t) * CL_PLANE + rowoff;
        reinterpret_cast<uint4*>(dst + p)[grp ^ key] = u;
    }
}

__global__ void convert_x_kernel(const float* __restrict__ x) {
    __shared__ float s[16][33];
    const int wp = blockIdx.x, t = blockIdx.y, b = blockIdx.z;
    const int w = wp - 1;
    const bool valid = ((unsigned)w < 32u);
    if (valid)
        for (int idx = threadIdx.x; idx < 512; idx += 256) {
            int ci = idx >> 5, hh = idx & 31;
            s[ci][hh] = x[(size_t)b * 16 * SP + (size_t)ci * SP + t * 1024 + w * 32 + hh];
        }
    __syncthreads();
    const int row = threadIdx.x >> 3, grp = threadIdx.x & 7, key = row & 7;
    uint4 u;
    uint32_t* pu = &u.x;
#pragma unroll
    for (int q = 0; q < 4; ++q) {
        float v[2];
#pragma unroll
        for (int e = 0; e < 2; ++e) {
            int kk = grp * 8 + 2 * q + e;
            int dh = kk >> 4, ci = kk & 15, hs = row + dh - 1;
            v[e] = (valid && kk < 48 && (unsigned)hs < 32u) ? s[ci][hs] : 0.f;
        }
        pu[q] = packh2(v[0], v[1]);
    }
    size_t p = ((size_t)b * 4 + t) * CL_PLANE + (size_t)(wp * 32 + row) * 64;
    reinterpret_cast<uint4*>(g_Xcl + p)[grp ^ key] = u;
}

// ---------------- HMMA implicit-GEMM conv, bulk-async double-buffered ----------------
// Block: 256 rows x 64 co; 8 warps = 4 rowgroups(64) x 2 cohalves(32).
// Dyn smem: 128 pad + 2 slots x (A 40960 + B 24576) = 131072
#define SLOT  65536
#define DSMEM (131072 + 128)

__global__ void __launch_bounds__(256, 1)
conv_mma_kernel(int mode, const float* __restrict__ bx, const float* __restrict__ bh) {
    extern __shared__ char dsm[];
    __shared__ __align__(8) unsigned long long s_mbar[2];
    __shared__ const __half* s_ap[20];
    __shared__ const __half* s_bp[20];
    __shared__ int s_nch[20];
    __shared__ int s_G;

    const uint32_t sb0 = (smem_u32(dsm) + 127u) & ~127u;
    char* base = dsm + (sb0 - smem_u32(dsm));
    const uint32_t mb0 = smem_u32(s_mbar);
    const int tid = threadIdx.x, warp = tid >> 5, lane = tid & 31;
    const int wq = blockIdx.x, t0 = blockIdx.y;
    int b, k;
    if (mode == 0) { b = blockIdx.z & 7; k = blockIdx.z >> 3; }
    else           { b = blockIdx.z;     k = 6; }
    const int rg = warp & 3;
    const int cbase = (warp >> 2) * 32;
    const int rA  = (lane & 7) + ((lane >> 3) & 1) * 8;
    const int kgA = lane >> 4;
    const int nB  = (lane & 7) + ((lane >> 4) & 1) * 8;
    const int kgB = (lane >> 3) & 1;

    if (tid == 0) {
        int G = 0;
        const size_t atile = (size_t)wq * 256 * 64;
        if (mode == 0) {
            const __half* st = (k < 3 || k == 6) ? g_Hcl : g_Mcl;
            for (int dt = 0; dt < 3; ++dt) {
                int t = t0 + dt - 1;
                if ((unsigned)t >= 4u) continue;
                for (int dh = 0; dh < 3; ++dh) {
                    s_ap[G] = st + ((size_t)(dh * 8 + b) * 4 + t) * CL_PLANE + atile;
                    s_bp[G] = g_whB + (size_t)(((k * 3 + dt) * 3 + dh) * 3) * 4096;
                    s_nch[G] = 4; ++G;
                }
            }
            for (int dt = 0; dt < 3; ++dt) {
                int t = t0 + dt - 1;
                if ((unsigned)t >= 4u) continue;
                s_ap[G] = g_Xcl + ((size_t)b * 4 + t) * CL_PLANE + atile;
                s_bp[G] = g_wxB + (size_t)(k * 9 + dt * 3) * 4096;
                s_nch[G] = 3; ++G;
            }
        } else {
            for (int src = 0; src < 2; ++src) {
                const __half* st = src ? g_MNcl : g_Ccl;
                for (int dt = 0; dt < 3; ++dt) {
                    int t = t0 + dt - 1;
                    if ((unsigned)t >= 4u) continue;
                    for (int dh = 0; dh < 3; ++dh) {
                        s_ap[G] = st + ((size_t)(dh * 8 + b) * 4 + t) * CL_PLANE + atile;
                        s_bp[G] = g_whB + (size_t)((((7 + src) * 3 + dt) * 3 + dh) * 3) * 4096;
                        s_nch[G] = 4; ++G;
                    }
                }
            }
        }
        s_G = G;
        asm volatile("mbarrier.init.shared.b64 [%0], %1;" :: "r"(mb0), "r"(1u) : "memory");
        asm volatile("mbarrier.init.shared.b64 [%0], %1;" :: "r"(mb0 + 8), "r"(1u) : "memory");
    }
    __syncthreads();
    const int G = s_G;

#define ISSUE(g) do { \
    uint32_t mbs = mb0 + ((g) & 1) * 8; \
    uint32_t dst = sb0 + (uint32_t)((g) & 1) * SLOT; \
    asm volatile("mbarrier.arrive.expect_tx.shared.b64 _, [%0], %1;" :: "r"(mbs), "r"(65536u) : "memory"); \
    asm volatile("cp.async.bulk.shared::cluster.global.mbarrier::complete_tx::bytes [%0], [%1], %2, [%3];" \
        :: "r"(dst), "l"((unsigned long long)(uintptr_t)s_ap[g]), "r"(40960u), "r"(mbs) : "memory"); \
    asm volatile("cp.async.bulk.shared::cluster.global.mbarrier::complete_tx::bytes [%0], [%1], %2, [%3];" \
        :: "r"(dst + 40960u), "l"((unsigned long long)(uintptr_t)s_bp[g]), "r"(24576u), "r"(mbs) : "memory"); \
} while (0)

    if (tid == 0) {
        ISSUE(0);
        if (G > 1) ISSUE(1);
    }

    float acc[4][4][4];
#pragma unroll
    for (int i = 0; i < 4; ++i)
#pragma unroll
        for (int j = 0; j < 4; ++j)
#pragma unroll
            for (int q = 0; q < 4; ++q) acc[i][j][q] = 0.f;

    for (int g = 0; g < G; ++g) {
        const int s = g & 1;
        mbar_wait(mb0 + s * 8, (uint32_t)((g >> 1) & 1));
        const uint32_t sA = sb0 + s * SLOT;
        const uint32_t sBB = sA + 40960u;
        const int nch = s_nch[g];
#pragma unroll
        for (int dw = 0; dw < 3; ++dw) {
            for (int c = 0; c < nch; ++c) {
                uint32_t bfr[4][2];
#pragma unroll
                for (int ntp = 0; ntp < 2; ++ntp) {
                    int corow = cbase + ntp * 16 + nB;
                    uint32_t addr = sBB + dw * 8192 + corow * 128
                                  + (((2 * c + kgB) ^ (corow & 7)) << 4);
                    uint32_t rr[4];
                    ldm4(rr, addr);
                    bfr[ntp * 2][0] = rr[0]; bfr[ntp * 2][1] = rr[1];
                    bfr[ntp * 2 + 1][0] = rr[2]; bfr[ntp * 2 + 1][1] = rr[3];
                }
#pragma unroll
                for (int rt = 0; rt < 4; ++rt) {
                    int row = rg * 64 + rt * 16 + rA + dw * 32;
                    uint32_t addr = sA + row * 128 + (((2 * c + kgA) ^ (lane & 7)) << 4);
                    uint32_t afr[4];
                    ldm4(afr, addr);
#pragma unroll
                    for (int nt = 0; nt < 4; ++nt)
                        mma16816(acc[rt][nt], afr, bfr[nt][0], bfr[nt][1]);
                }
            }
        }
        __syncthreads();                       // all reads of slot s done
        if (tid == 0 && g + 2 < G) ISSUE(g + 2);
    }

    // epilogue: stage D in smem (slot0 region), coalesced [co][spatial] writes
    float* so = reinterpret_cast<float*>(base);   // 64 co x 256 rows
#pragma unroll
    for (int rt = 0; rt < 4; ++rt)
#pragma unroll
        for (int nt = 0; nt < 4; ++nt) {
            int row0 = rg * 64 + rt * 16 + (lane >> 2);
            int co0 = cbase + nt * 8 + (lane & 3) * 2;
            so[co0 * 256 + (row0 ^ ((co0 & 7) << 2))] = acc[rt][nt][0];
            so[(co0 + 1) * 256 + (row0 ^ (((co0 + 1) & 7) << 2))] = acc[rt][nt][1];
            int row1 = row0 + 8;
            so[co0 * 256 + (row1 ^ ((co0 & 7) << 2))] = acc[rt][nt][2];
            so[(co0 + 1) * 256 + (row1 ^ (((co0 + 1) & 7) << 2))] = acc[rt][nt][3];
        }
    __syncthreads();
#pragma unroll
    for (int ci = 0; ci < 8; ++ci) {
        int co = warp * 8 + ci;
        float bias = (mode == 0) ? (bx[k * 64 + co] + bh[k * 64 + co])
                                 : (bh[448 + co] + bh[512 + co]);
        float* up = g_u + (size_t)k * VOL + (size_t)b * CSP + (size_t)co * SP
                  + t0 * 1024 + wq * 256;
        const int xr = (co & 7) << 2;
#pragma unroll
        for (int j = 0; j < 8; ++j) {
            int row = lane + 32 * j;
            float v = so[co * 256 + (row ^ xr)] + bias;
            if (mode == 0) up[row] = v; else up[row] += v;
        }
    }
    __syncthreads();
    if (tid == 0) {
        asm volatile("mbarrier.inval.shared.b64 [%0];" :: "r"(mb0) : "memory");
        asm volatile("mbarrier.inval.shared.b64 [%0];" :: "r"(mb0 + 8) : "memory");
    }
#undef ISSUE
}

// ---------------- LN3 + act ----------------
__global__ void ln3_act_kernel(int kbase) {
    __shared__ float sh[32];
    const int k = kbase + blockIdx.y;
    float* buf = g_u + (size_t)k * VOL + (size_t)blockIdx.x * SP;
    const int tid = threadIdx.x;
    float v[16], s = 0.f, sq = 0.f;
#pragma unroll
    for (int j = 0; j < 16; ++j) {
        v[j] = buf[tid + j * 256];
        s += v[j]; sq += v[j] * v[j];
    }
    block_reduce2(s, sq, sh);
    const float mu = s * (1.f / 4096.f);
    const float var = sq * (1.f / 4096.f) - mu * mu;
    const float rstd = rsqrtf(var + EPSF);
    const bool ist = (k == 2 || k == 4);
#pragma unroll
    for (int j = 0; j < 16; ++j) {
        float y = (v[j] - mu) * rstd;
        buf[tid + j * 256] = ist ? tanhf(y) : (1.f / (1.f + expf(-y)));
    }
}

__global__ void scores_part_kernel(const float* __restrict__ ch) {
    __shared__ float sh[32];
    const int lb = blockIdx.x >> 4, chunk = blockIdx.x & 15;
    const int b = lb & 7;
    const float4* r4 = (const float4*)(g_u + (size_t)b * CSP) + chunk * 4096;
    const float4* c4 = (const float4*)(ch + (size_t)lb * CSP) + chunk * 4096;
    float s = 0.f;
    for (int i = threadIdx.x; i < 4096; i += 256) {
        float4 a = r4[i], c = c4[i];
        s += a.x * c.x + a.y * c.y + a.z * c.z + a.w * c.w;
    }
    float d = 0.f;
    block_reduce2(s, d, sh);
    if (threadIdx.x == 0) g_spart[blockIdx.x] = s;
}

__global__ void scores_softmax_kernel() {
    __shared__ float ssc[40];
    const int t = threadIdx.x;
    if (t < 40) {
        float s = 0.f;
        for (int j = 0; j < 16; ++j) s += g_spart[t * 16 + j];
        ssc[t] = s * (1.f / 64.f);
    }
    __syncthreads();
    if (t < 5) {
        const int l = t;
        float mx = -1e30f;
        for (int b = 0; b < 8; ++b) mx = fmaxf(mx, ssc[l * 8 + b]);
        float e[8], sum = 0.f;
        for (int b = 0; b < 8; ++b) { e[b] = expf(ssc[l * 8 + b] - mx); sum += e[b]; }
        float inv = 1.f / sum;
        for (int b = 0; b < 8; ++b) g_attn[l * 8 + b] = e[b] * inv;
    }
}

// z + LN4 partials + fused c_history shift (out[l] = c_{l+1}, l=0..3)
__global__ void zstats_kernel(const float* __restrict__ ch, float* __restrict__ out) {
    __shared__ float sh[32];
    const int b = blockIdx.x >> 8;
    const int off = (blockIdx.x & 255) * 1024;
    const float a0 = g_attn[b],      a1 = g_attn[8 + b], a2 = g_attn[16 + b];
    const float a3 = g_attn[24 + b], a4 = 1.f + g_attn[32 + b];
    const float* c0 = ch + (size_t)b * CSP;
    float* ob = out + (size_t)b * CSP;
    float s = 0.f, sq = 0.f;
#pragma unroll
    for (int j = 0; j < 4; ++j) {
        int i = off + threadIdx.x + j * 256;
        float v1 = c0[i + VOL], v2 = c0[i + 2 * VOL];
        float v3 = c0[i + 3 * VOL], v4 = c0[i + 4 * VOL];
        float z = a0 * c0[i] + a1 * v1 + a2 * v2 + a3 * v3 + a4 * v4;
        ob[i]           = v1;                 // history shift
        ob[i + VOL]     = v2;
        ob[i + 2 * VOL] = v3;
        ob[i + 3 * VOL] = v4;
        ob[i + 4 * VOL] = z;                  // z into c-slot
        s += z; sq += z * z;
    }
    block_reduce2(s, sq, sh);
    if (threadIdx.x == 0) { g_part[blockIdx.x * 2] = s; g_part[blockIdx.x * 2 + 1] = sq; }
}

__global__ void stats_reduce_kernel() {
    __shared__ float sh[32];
    const int b = blockIdx.x;
    float s  = g_part[(b * 256 + threadIdx.x) * 2];
    float sq = g_part[(b * 256 + threadIdx.x) * 2 + 1];
    block_reduce2(s, sq, sh);
    if (threadIdx.x == 0) { g_stats[b * 2] = s; g_stats[b * 2 + 1] = sq; }
}

__global__ void finalize_kernel(const float* __restrict__ m, const float* __restrict__ lnw,
                                const float* __restrict__ lnb, float* __restrict__ out) {
    const int base = blockIdx.x * 1024;
#pragma unroll
    for (int j = 0; j < 4; ++j) {
        int idx = base + threadIdx.x + j * 256;
        int b = idx >> 18;
        int cs = idx & (CSP - 1);
        float mu = g_stats[2 * b] * (1.f / (float)CSP);
        float var = g_stats[2 * b + 1] * (1.f / (float)CSP) - mu * mu;
        float rstd = rsqrtf(var + EPSF);
        float z = out[4 * VOL + idx];
        float c = g_u[1 * VOL + idx] * g_u[2 * VOL + idx] + (z - mu) * rstd * lnw[cs] + lnb[cs];
        float mn = g_u[3 * VOL + idx] * g_u[4 * VOL + idx] + g_u[5 * VOL + idx] * m[idx];
        out[4 * VOL + idx] = c;
        out[5 * VOL + idx] = mn;
    }
}

// ---------------- stage7 (FFMA2 GEMM) ----------------
__global__ void __launch_bounds__(256, 2)
stage7_kernel(float* __restrict__ out, const float* __restrict__ b111) {
    __shared__ __align__(16) float s_w[8192];
    const int b = blockIdx.z, t0 = blockIdx.y, wbase = blockIdx.x * 8;
    const int tid = threadIdx.x, wl = tid >> 5, hh = tid & 31;
    for (int idx = tid; idx < 2048; idx += 256)
        reinterpret_cast<float4*>(s_w)[idx] = reinterpret_cast<const float4*>(g_w111T)[idx];
    __syncthreads();
    const int pos = t0 * 1024 + (wbase + wl) * 32 + hh;
    const float* cb = out + (size_t)4 * VOL + (size_t)b * CSP + pos;
    const float* mb = out + (size_t)5 * VOL + (size_t)b * CSP + pos;
    unsigned long long acc[32];
#pragma unroll
    for (int i = 0; i < 32; ++i) acc[i] = 0ull;
    for (int half = 0; half < 2; ++half) {
        const float* src = half ? mb : cb;
        for (int ci0 = 0; ci0 < 64; ci0 += 8) {
            float v[8];
#pragma unroll
            for (int j = 0; j < 8; ++j) v[j] = src[(size_t)(ci0 + j) * SP];
#pragma unroll
            for (int j = 0; j < 8; ++j) {
                unsigned long long vv = bcast2(v[j]);
                const ulonglong2* wq = reinterpret_cast<const ulonglong2*>(
                    s_w + (half * 64 + ci0 + j) * 64);
#pragma unroll
                for (int q = 0; q < 16; ++q) {
                    ulonglong2 wp = wq[q];
                    ffma2(acc[2 * q], vv, wp.x);
                    ffma2(acc[2 * q + 1], vv, wp.y);
                }
            }
        }
    }
    const float* ob = g_u + (size_t)6 * VOL + (size_t)b * CSP + pos;
    float* hb = out + (size_t)6 * VOL + (size_t)b * CSP + pos;
#pragma unroll
    for (int cp = 0; cp < 32; ++cp) {
        float lo, hi; unpack2(acc[cp], lo, hi);
        int co = 2 * cp;
        hb[(size_t)co * SP]       = ob[(size_t)co * SP]       * tanhf(lo + b111[co]);
        hb[(size_t)(co + 1) * SP] = ob[(size_t)(co + 1) * SP] * tanhf(hi + b111[co + 1]);
    }
}

// ---------------- host ----------------
extern "C" void kernel_launch(void* const* d_in, const int* in_sizes, int n_in,
                              void* d_out, int out_size) {
    (void)in_sizes; (void)n_in; (void)out_size;
    const float* x    = (const float*)d_in[0];
    const float* ch   = (const float*)d_in[1];
    const float* m    = (const float*)d_in[2];
    const float* h    = (const float*)d_in[3];
    const float* Wx   = (const float*)d_in[4];
    const float* bx   = (const float*)d_in[5];
    const float* Wh   = (const float*)d_in[6];
    const float* bh   = (const float*)d_in[7];
    const float* w111 = (const float*)d_in[8];
    const float* b111 = (const float*)d_in[9];
    const float* lnw  = (const float*)d_in[10];
    const float* lnb  = (const float*)d_in[11];
    float* out = (float*)d_out;

    cudaFuncSetAttribute(conv_mma_kernel, cudaFuncAttributeMaxDynamicSharedMemorySize, DSMEM);

    prep_kernel<<<4928, 256>>>(Wx, Wh, w111);
    convert_x_kernel<<<dim3(34, 4, 8), 256>>>(x);
    convert_state_kernel<<<dim3(34, 4, 8), 256>>>(h, 0);
    convert_state_kernel<<<dim3(34, 4, 8), 256>>>(m, 1);
    conv_mma_kernel<<<dim3(4, 4, 56), 256, DSMEM>>>(0, bx, bh);   // u0..u6 pre-acts
    ln3_act_kernel<<<dim3(512, 6), 256>>>(0);                     // r,i,g,i',g',f'
    scores_part_kernel<<<640, 256>>>(ch);
    scores_softmax_kernel<<<1, 64>>>();
    zstats_kernel<<<2048, 256>>>(ch, out);                        // z + stats + shift
    stats_reduce_kernel<<<8, 256>>>();
    finalize_kernel<<<2048, 256>>>(m, lnw, lnb, out);             // c, m_new
    convert_state_kernel<<<dim3(34, 4, 8), 256>>>(out + (size_t)4 * VOL, 2);
    convert_state_kernel<<<dim3(34, 4, 8), 256>>>(out + (size_t)5 * VOL, 3);
    conv_mma_kernel<<<dim3(4, 4, 8), 256, DSMEM>>>(1, bx, bh);    // u6 += convs
    ln3_act_kernel<<<dim3(512, 1), 256>>>(6);                     // o
    stage7_kernel<<<dim3(4, 4, 8), 256>>>(out, b111);             // h_new
}